// round 2
// baseline (speedup 1.0000x reference)
#include <cuda_runtime.h>
#include <math.h>

// ---------------------------------------------------------------------------
// Problem constants
// ---------------------------------------------------------------------------
#define CNUM 32      // channels
#define KS   3       // base kernel
#define RS   11      // effective kernel (K + 2*(EXP_NITER-1) = 3+8)
#define BAT  16
#define HW   256
#define TILE 16
#define HALO (TILE + RS - 1)   // 26
#define XS   27                // padded smem row stride for x tile
#define POWER_IT 3

// ---------------------------------------------------------------------------
// Device scratch (static; no allocations allowed)
// ---------------------------------------------------------------------------
__device__ float g_sk[CNUM*CNUM*KS*KS];        // skewed + sigma-normalized kernel
__device__ float g_buf[2][CNUM*CNUM*RS*RS];    // conv-exp ping-pong
__device__ float g_w [CNUM*CNUM*RS*RS];        // final 11x11 weight (kg)

// ---------------------------------------------------------------------------
// Block-wide helpers (blockDim.x == 1024)
// ---------------------------------------------------------------------------
__device__ __forceinline__ float blk_reduce(float v, float* red) {
    int tid = threadIdx.x;
    red[tid] = v;
    __syncthreads();
    for (int s = 512; s >= 1; s >>= 1) {
        if (tid < s) red[tid] += red[tid + s];
        __syncthreads();
    }
    float r = red[0];
    __syncthreads();
    return r;
}

__device__ __forceinline__ void blk_l2n(float* a, int n, float* red) {
    int tid = threadIdx.x;
    float p = 0.f;
    for (int i = tid; i < n; i += 1024) p += a[i] * a[i];
    float s = blk_reduce(p, red);
    float scale = 1.0f / (sqrtf(s) + 1e-12f);
    for (int i = tid; i < n; i += 1024) a[i] *= scale;
    __syncthreads();
}

// ---------------------------------------------------------------------------
// Kernel 1: skew + FantasticFour (single block, everything in smem)
// ---------------------------------------------------------------------------
__global__ void __launch_bounds__(1024) prep_ff(
    const float* __restrict__ raw,
    const float* __restrict__ u1i, const float* __restrict__ u2i,
    const float* __restrict__ u3i, const float* __restrict__ u4i)
{
    __shared__ float sk[CNUM*CNUM*KS*KS];   // 9216 floats = 36 KB
    __shared__ float su1[96], sv1[96], su2[96], sv2[96];
    __shared__ float su3[288], sv3[32], su4[288], sv4[32];
    __shared__ float red[1024];

    int tid = threadIdx.x;

    // skew: sk[o,c,h,w] = raw[o,c,h,w] - raw[c,o,2-h,2-w]
    for (int i = tid; i < 9216; i += 1024) {
        int o = i / 288, r = i % 288;
        int c = r / 9, h = (r % 9) / 3, w = r % 3;
        sk[i] = raw[i] - raw[((c*32 + o)*3 + (2 - h))*3 + (2 - w)];
    }
    if (tid < 96)  su1[tid] = u1i[tid];
    if (tid < 96)  su2[tid] = u2i[tid];
    if (tid < 288) su3[tid] = u3i[tid];
    if (tid < 288) su4[tid] = u4i[tid];
    __syncthreads();

    blk_l2n(su1, 96, red);
    blk_l2n(su2, 96, red);
    blk_l2n(su3, 288, red);
    blk_l2n(su4, 288, red);

    for (int it = 0; it < POWER_IT; it++) {
        // v1[o,h] = sum_{c,w} k[o,c,h,w] * u1[c,w]
        if (tid < 96) {
            int o = tid / 3, h = tid % 3;
            float s = 0.f;
            for (int c = 0; c < 32; c++)
                for (int w = 0; w < 3; w++)
                    s += sk[((o*32 + c)*3 + h)*3 + w] * su1[c*3 + w];
            sv1[tid] = s;
        }
        __syncthreads();
        blk_l2n(sv1, 96, red);
        // u1[c,w] = sum_{o,h} k[o,c,h,w] * v1[o,h]
        if (tid < 96) {
            int c = tid / 3, w = tid % 3;
            float s = 0.f;
            for (int o = 0; o < 32; o++)
                for (int h = 0; h < 3; h++)
                    s += sk[((o*32 + c)*3 + h)*3 + w] * sv1[o*3 + h];
            su1[tid] = s;
        }
        __syncthreads();
        blk_l2n(su1, 96, red);

        // v2[o,w] = sum_{c,h} k * u2[c,h]
        if (tid < 96) {
            int o = tid / 3, w = tid % 3;
            float s = 0.f;
            for (int c = 0; c < 32; c++)
                for (int h = 0; h < 3; h++)
                    s += sk[((o*32 + c)*3 + h)*3 + w] * su2[c*3 + h];
            sv2[tid] = s;
        }
        __syncthreads();
        blk_l2n(sv2, 96, red);
        // u2[c,h] = sum_{o,w} k * v2[o,w]
        if (tid < 96) {
            int c = tid / 3, h = tid % 3;
            float s = 0.f;
            for (int o = 0; o < 32; o++)
                for (int w = 0; w < 3; w++)
                    s += sk[((o*32 + c)*3 + h)*3 + w] * sv2[o*3 + w];
            su2[tid] = s;
        }
        __syncthreads();
        blk_l2n(su2, 96, red);

        // v3[o] = sum_{c,h,w} k * u3[c,h,w]
        if (tid < 32) {
            float s = 0.f;
            for (int j = 0; j < 288; j++) {
                int c = j / 9, h = (j % 9) / 3, w = j % 3;
                s += sk[((tid*32 + c)*3 + h)*3 + w] * su3[j];
            }
            sv3[tid] = s;
        }
        __syncthreads();
        blk_l2n(sv3, 32, red);
        // u3[c,h,w] = sum_o k * v3[o]
        if (tid < 288) {
            int c = tid / 9, h = (tid % 9) / 3, w = tid % 3;
            float s = 0.f;
            for (int o = 0; o < 32; o++)
                s += sk[((o*32 + c)*3 + h)*3 + w] * sv3[o];
            su3[tid] = s;
        }
        __syncthreads();
        blk_l2n(su3, 288, red);

        // v4[c] = sum_{o,h,w} k * u4[o,h,w]
        if (tid < 32) {
            float s = 0.f;
            for (int j = 0; j < 288; j++) {
                int o = j / 9, h = (j % 9) / 3, w = j % 3;
                s += sk[((o*32 + tid)*3 + h)*3 + w] * su4[j];
            }
            sv4[tid] = s;
        }
        __syncthreads();
        blk_l2n(sv4, 32, red);
        // u4[o,h,w] = sum_c k * v4[c]
        if (tid < 288) {
            int o = tid / 9, h = (tid % 9) / 3, w = tid % 3;
            float s = 0.f;
            for (int c = 0; c < 32; c++)
                s += sk[((o*32 + c)*3 + h)*3 + w] * sv4[c];
            su4[tid] = s;
        }
        __syncthreads();
        blk_l2n(su4, 288, red);
    }

    // sigmas
    float p1 = 0.f, p2 = 0.f, p3 = 0.f, p4 = 0.f;
    for (int i = tid; i < 9216; i += 1024) {
        int o = i / 288, r = i % 288;
        int c = r / 9, h = (r % 9) / 3, w = r % 3;
        float k = sk[i];
        p1 += k * su1[c*3 + w]         * sv1[o*3 + h];
        p2 += k * su2[c*3 + h]         * sv2[o*3 + w];
        p3 += k * su3[c*9 + h*3 + w]   * sv3[o];
        p4 += k * su4[o*9 + h*3 + w]   * sv4[c];
    }
    float s1 = blk_reduce(p1, red);
    float s2 = blk_reduce(p2, red);
    float s3 = blk_reduce(p3, red);
    float s4 = blk_reduce(p4, red);
    float sigma = fminf(fminf(s1, s2), fminf(s3, s4));
    float inv = 1.0f / sigma;
    for (int i = tid; i < 9216; i += 1024) g_sk[i] = sk[i] * inv;
}

// ---------------------------------------------------------------------------
// Kernel 2: kg init — kg = pad(kernel + I) centered in 11x11
// ---------------------------------------------------------------------------
__global__ void init_kg() {
    int idx = blockIdx.x * blockDim.x + threadIdx.x;
    if (idx >= CNUM*CNUM*RS*RS) return;
    int x = idx % RS, y = (idx / RS) % RS;
    int d = (idx / (RS*RS)) % CNUM, o = idx / (RS*RS*CNUM);
    float v = 0.f;
    if (y >= 4 && y <= 6 && x >= 4 && x <= 6) {
        v = g_sk[((o*32 + d)*3 + (y - 4))*3 + (x - 4)];
        if (o == d && y == 5 && x == 5) v += 1.0f;
    }
    g_w[idx] = v;
}

// ---------------------------------------------------------------------------
// Kernel 3: one conv-exponential composition step + kg accumulation
// out[o,d,y,x] = (1/i) * sum_{c,p,q} ki[c,d,y-p,x-q] * g_sk[o,c,p,q]
// ---------------------------------------------------------------------------
__global__ void conv_exp_step(int in_sel, int out_sel, int Sin, int Sout,
                              float inv_i, int off) {
    int idx = blockIdx.x * blockDim.x + threadIdx.x;
    int total = CNUM*CNUM*Sout*Sout;
    if (idx >= total) return;
    int x = idx % Sout, y = (idx / Sout) % Sout;
    int d = (idx / (Sout*Sout)) % CNUM, o = idx / (Sout*Sout*CNUM);

    const float* kin = (in_sel < 0) ? g_sk : g_buf[in_sel];
    float acc = 0.f;
    for (int c = 0; c < 32; c++) {
        const float* kb = kin + (c*32 + d)*Sin*Sin;
        const float* wb = g_sk + (o*32 + c)*9;
        #pragma unroll
        for (int p = 0; p < 3; p++) {
            int yy = y - p;
            if (yy < 0 || yy >= Sin) continue;
            #pragma unroll
            for (int q = 0; q < 3; q++) {
                int xx = x - q;
                if (xx < 0 || xx >= Sin) continue;
                acc += kb[yy*Sin + xx] * wb[p*3 + q];
            }
        }
    }
    acc *= inv_i;
    g_buf[out_sel][idx] = acc;
    g_w[((o*32 + d)*RS + off + y)*RS + off + x] += acc;
}

// ---------------------------------------------------------------------------
// Kernel 4: main circular 11x11 conv, fp32 register-blocked.
// Block: 256 threads -> 16x16 pixel tile x 32 c_out.
// Thread: 4 pixels (same column, rows ry+{0,4,8,12}) x 8 c_out = 32 accums.
// ---------------------------------------------------------------------------
__global__ void __launch_bounds__(256, 2) conv_main(
    const float* __restrict__ x,
    const float* __restrict__ bias,
    float* __restrict__ out)
{
    // NOTE: sw is read via float4 — must be 16B-aligned explicitly (R1 fault:
    // consecutive shared arrays are only element-aligned).
    __shared__ __align__(16) float sw[RS*RS * CNUM];  // 121*32 floats, layout [k][o]
    __shared__ __align__(16) float sx[HALO * XS];     // 26*27 floats

    const int tid = threadIdx.x;
    const int b   = blockIdx.z;
    const int ty0 = blockIdx.y * TILE;
    const int tx0 = blockIdx.x * TILE;

    const int grp   = tid >> 6;        // 0..3  -> c_out group
    const int tp    = tid & 63;        // 0..63
    const int obase = grp * 8;
    const int px    = tp & 15;         // column within tile
    const int ry    = tp >> 4;         // base row (rows ry, ry+4, ry+8, ry+12)

    float acc[4][8];
    #pragma unroll
    for (int j = 0; j < 4; j++)
        #pragma unroll
        for (int o = 0; o < 8; o++) acc[j][o] = 0.f;

    const float* xb = x + (size_t)b * CNUM * HW * HW;

    for (int c = 0; c < CNUM; c++) {
        __syncthreads();
        // stage x halo tile (with circular wrap)
        const float* xc = xb + c * HW * HW;
        for (int i = tid; i < HALO*HALO; i += 256) {
            int r  = i / HALO, cc = i % HALO;
            int gy = (ty0 + r  - 5 + HW) & (HW - 1);
            int gx = (tx0 + cc - 5 + HW) & (HW - 1);
            sx[r*XS + cc] = xc[gy*HW + gx];
        }
        // stage weights transposed: sw[k*32 + o] = w[o,c,k]
        for (int i = tid; i < RS*RS*CNUM; i += 256) {
            int k = i >> 5, o = i & 31;
            sw[i] = g_w[(o*32 + c)*(RS*RS) + k];
        }
        __syncthreads();

        for (int ky = 0; ky < RS; ky++) {
            const float* sxr = sx + (ry + ky) * XS + px;
            const float* swr = sw + ky * RS * 32 + obase;
            #pragma unroll
            for (int kx = 0; kx < RS; kx++) {
                float4 w0 = *(const float4*)(swr + kx*32);
                float4 w1 = *(const float4*)(swr + kx*32 + 4);
                #pragma unroll
                for (int j = 0; j < 4; j++) {
                    float xv = sxr[j*4*XS + kx];
                    acc[j][0] += xv * w0.x;
                    acc[j][1] += xv * w0.y;
                    acc[j][2] += xv * w0.z;
                    acc[j][3] += xv * w0.w;
                    acc[j][4] += xv * w1.x;
                    acc[j][5] += xv * w1.y;
                    acc[j][6] += xv * w1.z;
                    acc[j][7] += xv * w1.w;
                }
            }
        }
    }

    // epilogue: + bias, store
    float bv[8];
    #pragma unroll
    for (int o = 0; o < 8; o++) bv[o] = __ldg(&bias[obase + o]);

    #pragma unroll
    for (int j = 0; j < 4; j++) {
        int oy = ty0 + ry + 4*j;
        #pragma unroll
        for (int o = 0; o < 8; o++) {
            out[(((size_t)b*CNUM + obase + o)*HW + oy)*HW + tx0 + px] =
                acc[j][o] + bv[o];
        }
    }
}

// ---------------------------------------------------------------------------
// Launcher
// ---------------------------------------------------------------------------
extern "C" void kernel_launch(void* const* d_in, const int* in_sizes, int n_in,
                              void* d_out, int out_size) {
    const float* x    = (const float*)d_in[0];
    const float* raw  = (const float*)d_in[1];
    const float* bias = (const float*)d_in[2];
    const float* u1   = (const float*)d_in[3];
    const float* u2   = (const float*)d_in[4];
    const float* u3   = (const float*)d_in[5];
    const float* u4   = (const float*)d_in[6];
    float* out = (float*)d_out;

    // 1) skew + FantasticFour -> g_sk
    prep_ff<<<1, 1024>>>(raw, u1, u2, u3, u4);

    // 2) kg = centered (kernel + I)
    init_kg<<<(CNUM*CNUM*RS*RS + 255) / 256, 256>>>();

    // 3) conv-exponential steps (i = 2..5), accumulating into g_w
    //    (in_sel, out_sel, Sin, Sout, 1/i, center offset)
    {
        int t;
        t = CNUM*CNUM*5*5;   conv_exp_step<<<(t+255)/256, 256>>>(-1, 0, 3,  5, 1.0f/2.0f, 3);
        t = CNUM*CNUM*7*7;   conv_exp_step<<<(t+255)/256, 256>>>( 0, 1, 5,  7, 1.0f/3.0f, 2);
        t = CNUM*CNUM*9*9;   conv_exp_step<<<(t+255)/256, 256>>>( 1, 0, 7,  9, 1.0f/4.0f, 1);
        t = CNUM*CNUM*11*11; conv_exp_step<<<(t+255)/256, 256>>>( 0, 1, 9, 11, 1.0f/5.0f, 0);
    }

    // 4) main conv
    dim3 grid(HW / TILE, HW / TILE, BAT);   // (16,16,16)
    conv_main<<<grid, 256>>>(x, bias, out);
}